// round 15
// baseline (speedup 1.0000x reference)
#include <cuda_runtime.h>
#include <cuda_fp16.h>

#define N_NODES 100000
#define DIM 64
#define R 5
#define E 500000
#define NEDGE (R * E)  // 2.5M per direction
#define SCAN_BLOCKS 128
#define SCAN_CH ((N_NODES + SCAN_BLOCKS - 1) / SCAN_BLOCKS)  // 782
#define SCAN_SUB ((SCAN_CH + 255) / 256)                     // 4
#define XPITCH 72  // halves; pitch-72 makes all fragment LDS conflict-free

// Per-relation, per-direction transformed features in fp16: 128 MB (~L2-sized).
__device__ __align__(16) __half g_tmp[(size_t)R * 2 * N_NODES * DIM];
// Cumulative weights, fp16, TRANSPOSED [r][o][d] (o-major) per direction.
__device__ __align__(16) __half g_WcT_u[R * DIM * DIM];
__device__ __align__(16) __half g_WcT_v[R * DIM * DIM];

// CSR structures (destination-sorted edge lists), per direction.
__device__ int g_deg[2][N_NODES];
__device__ int g_offs[2][N_NODES + 1];
__device__ int g_bsum[2 * SCAN_BLOCKS];
__device__ int g_bbase[2 * SCAN_BLOCKS];
__device__ int g_rank_u[NEDGE];  // within-node rank captured during hist
__device__ int g_rank_v[NEDGE];
__device__ __align__(16) int2 g_ent_u[NEDGE];  // {tmp_row_idx, bits(val)}
__device__ __align__(16) int2 g_ent_v[NEDGE];

// ---------------------------------------------------------------------------
// Cumsum of weights + fp16 transpose: g_WcT[r][o*64+d] = fp16(cumsum W[.][d][o]).
// ---------------------------------------------------------------------------
__global__ void cumsum_kernel(const float* __restrict__ wu,
                              const float* __restrict__ wv) {
    int t = blockIdx.x * blockDim.x + threadIdx.x;
    if (t >= DIM * DIM) return;
    int d = t >> 6, o = t & 63;
    float a = 0.f, b = 0.f;
#pragma unroll
    for (int r = 0; r < R; r++) {
        a += wu[r * DIM * DIM + t];
        b += wv[r * DIM * DIM + t];
        g_WcT_u[r * DIM * DIM + o * DIM + d] = __float2half_rn(a);
        g_WcT_v[r * DIM * DIM + o * DIM + d] = __float2half_rn(b);
    }
}

// ---------------------------------------------------------------------------
__global__ void zero_deg_kernel() {
    int i = blockIdx.x * blockDim.x + threadIdx.x;
    if (i < N_NODES) {
        g_deg[0][i] = 0;
        g_deg[1][i] = 0;
    }
}

// ---------------------------------------------------------------------------
// Degree histogram + rank capture: the atomicAdd return value IS the edge's
// within-node rank; storing it makes fill_kernel atomic-free.
// ---------------------------------------------------------------------------
__global__ __launch_bounds__(256) void hist_kernel(
    const int* __restrict__ edge_u, const int* __restrict__ edge_v) {
    long i = (long)blockIdx.x * blockDim.x + threadIdx.x;
    if (i >= NEDGE) return;
    g_rank_u[i] = atomicAdd(&g_deg[0][__ldg(edge_u + i)], 1);
    g_rank_v[i] = atomicAdd(&g_deg[1][__ldg(edge_v + i)], 1);
}

// ---------------------------------------------------------------------------
__global__ __launch_bounds__(256) void partial_kernel() {
    __shared__ int s[256];
    const int dir = blockIdx.y;
    const int base = blockIdx.x * SCAN_CH;
    const int t = threadIdx.x;
    int sum = 0;
    for (int i = t; i < SCAN_CH; i += 256) {
        int n = base + i;
        if (n < N_NODES) sum += g_deg[dir][n];
    }
    s[t] = sum;
    __syncthreads();
    for (int off = 128; off > 0; off >>= 1) {
        if (t < off) s[t] += s[t + off];
        __syncthreads();
    }
    if (t == 0) g_bsum[dir * SCAN_BLOCKS + blockIdx.x] = s[0];
}

// ---------------------------------------------------------------------------
__global__ __launch_bounds__(2 * SCAN_BLOCKS) void scan_bsums_kernel() {
    __shared__ int s[2 * SCAN_BLOCKS];
    const int t = threadIdx.x;
    const int idx = t & (SCAN_BLOCKS - 1);
    int my = g_bsum[t];
    s[t] = my;
    __syncthreads();
    for (int off = 1; off < SCAN_BLOCKS; off <<= 1) {
        int v = (idx >= off) ? s[t - off] : 0;
        __syncthreads();
        s[t] += v;
        __syncthreads();
    }
    g_bbase[t] = s[t] - my;  // exclusive
    if (idx == SCAN_BLOCKS - 1) g_offs[t >> 7][N_NODES] = s[t];
}

// ---------------------------------------------------------------------------
__global__ __launch_bounds__(256) void offsets_kernel() {
    __shared__ int s[256];
    const int dir = blockIdx.y;
    const int cbase = blockIdx.x * SCAN_CH;
    const int t = threadIdx.x;
    const int beg = cbase + t * SCAN_SUB;
    const int end = min(beg + SCAN_SUB, min(cbase + SCAN_CH, N_NODES));

    int d[SCAN_SUB];
    int sum = 0;
#pragma unroll
    for (int j = 0; j < SCAN_SUB; j++) {
        int n = beg + j;
        d[j] = (n < end) ? g_deg[dir][n] : 0;
        sum += d[j];
    }
    s[t] = sum;
    __syncthreads();
    for (int off = 1; off < 256; off <<= 1) {
        int v = (t >= off) ? s[t - off] : 0;
        __syncthreads();
        s[t] += v;
        __syncthreads();
    }
    int run = g_bbase[dir * SCAN_BLOCKS + blockIdx.x] + s[t] - sum;
#pragma unroll
    for (int j = 0; j < SCAN_SUB; j++) {
        int n = beg + j;
        if (n < end) {
            g_offs[dir][n] = run;
            run += d[j];
        }
    }
}

// ---------------------------------------------------------------------------
// Fill CSR entries — atomic-free: position = offs[dst] + captured rank.
// ---------------------------------------------------------------------------
__global__ __launch_bounds__(256) void fill_kernel(
    const float* __restrict__ edge_val, const int* __restrict__ edge_u,
    const int* __restrict__ edge_v) {
    long i = (long)blockIdx.x * blockDim.x + threadIdx.x;
    if (i >= NEDGE) return;
    const int r = (int)(i / E);
    const int u = __ldg(edge_u + i);
    const int v = __ldg(edge_v + i);
    const int vb = __float_as_int(__ldg(edge_val + i));

    int pu = __ldg(&g_offs[0][u]) + g_rank_u[i];
    g_ent_u[pu] = make_int2((r * 2 + 1) * N_NODES + v, vb);
    int pv = __ldg(&g_offs[1][v]) + g_rank_v[i];
    g_ent_v[pv] = make_int2((r * 2 + 0) * N_NODES + u, vb);
}

// ---------------------------------------------------------------------------
// Tensor-core tmp GEMM (unchanged from R14 — validated).
// ---------------------------------------------------------------------------
__device__ __forceinline__ void mma16816(float c[4], const unsigned a[4],
                                         const unsigned b[2]) {
    asm volatile(
        "mma.sync.aligned.m16n8k16.row.col.f32.f16.f16.f32 "
        "{%0,%1,%2,%3}, {%4,%5,%6,%7}, {%8,%9}, {%0,%1,%2,%3};"
        : "+f"(c[0]), "+f"(c[1]), "+f"(c[2]), "+f"(c[3])
        : "r"(a[0]), "r"(a[1]), "r"(a[2]), "r"(a[3]), "r"(b[0]), "r"(b[1]));
}

__global__ __launch_bounds__(256) void tmp_gemm_kernel(
    const float* __restrict__ x_u, const float* __restrict__ x_v) {
    __shared__ __half x_sh[128 * XPITCH];  // 18 KB
    __shared__ __half w_shT[64 * XPITCH];  // 9 KB, [o][d]

    const int dir = blockIdx.y;
    const float* __restrict__ X = dir ? x_v : x_u;
    const __half* __restrict__ WTbase = dir ? g_WcT_v : g_WcT_u;

    const int nbase = blockIdx.x * 128;
    const int tid = threadIdx.x;
    const int lane = tid & 31;
    const int wid = tid >> 5;
    const int m_base = (wid >> 1) * 32;  // warp M origin
    const int n0w = (wid & 1) * 32;      // warp N origin

    for (int i = tid; i < 128 * 16; i += 256) {
        int row = i >> 4, c4 = i & 15;
        int gn = nbase + row;
        float4 v = make_float4(0.f, 0.f, 0.f, 0.f);
        if (gn < N_NODES)
            v = reinterpret_cast<const float4*>(X + (size_t)gn * DIM)[c4];
        __half2* p = reinterpret_cast<__half2*>(x_sh + row * XPITCH + c4 * 4);
        p[0] = __floats2half2_rn(v.x, v.y);
        p[1] = __floats2half2_rn(v.z, v.w);
    }

    const int frow = lane >> 2;     // fragment row (m or n) index
    const int fk = (lane & 3) * 2;  // fragment k pair base

    for (int r = 0; r < R; r++) {
        __syncthreads();
        const uint4* WT =
            reinterpret_cast<const uint4*>(WTbase + r * DIM * DIM);
#pragma unroll
        for (int it = 0; it < 2; it++) {
            int i = tid + it * 256;
            int row = i >> 3, d8 = i & 7;
            *reinterpret_cast<uint4*>(w_shT + row * XPITCH + d8 * 8) = WT[i];
        }
        __syncthreads();

        float c[2][4][4];
#pragma unroll
        for (int mt = 0; mt < 2; mt++)
#pragma unroll
            for (int nt = 0; nt < 4; nt++)
#pragma unroll
                for (int j = 0; j < 4; j++) c[mt][nt][j] = 0.f;

#pragma unroll
        for (int k0 = 0; k0 < 64; k0 += 16) {
            unsigned a[2][4];
#pragma unroll
            for (int mt = 0; mt < 2; mt++) {
                const __half* base =
                    x_sh + (m_base + mt * 16 + frow) * XPITCH + k0 + fk;
                a[mt][0] = *reinterpret_cast<const unsigned*>(base);
                a[mt][1] = *reinterpret_cast<const unsigned*>(base + 8 * XPITCH);
                a[mt][2] = *reinterpret_cast<const unsigned*>(base + 8);
                a[mt][3] =
                    *reinterpret_cast<const unsigned*>(base + 8 * XPITCH + 8);
            }
            unsigned b[4][2];
#pragma unroll
            for (int nt = 0; nt < 4; nt++) {
                const __half* wb =
                    w_shT + (n0w + nt * 8 + frow) * XPITCH + k0 + fk;
                b[nt][0] = *reinterpret_cast<const unsigned*>(wb);
                b[nt][1] = *reinterpret_cast<const unsigned*>(wb + 8);
            }
#pragma unroll
            for (int mt = 0; mt < 2; mt++)
#pragma unroll
                for (int nt = 0; nt < 4; nt++) mma16816(c[mt][nt], a[mt], b[nt]);
        }

        __half* T = g_tmp + (size_t)(r * 2 + dir) * N_NODES * DIM;
        const int ccol = (lane & 3) * 2;
#pragma unroll
        for (int mt = 0; mt < 2; mt++) {
            int gn0 = nbase + m_base + mt * 16 + frow;
            int gn1 = gn0 + 8;
#pragma unroll
            for (int nt = 0; nt < 4; nt++) {
                int o = n0w + nt * 8 + ccol;
                if (gn0 < N_NODES)
                    *reinterpret_cast<__half2*>(T + (size_t)gn0 * DIM + o) =
                        __floats2half2_rn(c[mt][nt][0], c[mt][nt][1]);
                if (gn1 < N_NODES)
                    *reinterpret_cast<__half2*>(T + (size_t)gn1 * DIM + o) =
                        __floats2half2_rn(c[mt][nt][2], c[mt][nt][3]);
            }
        }
    }
}

// ---------------------------------------------------------------------------
// Gather (validated R12/R14 version): one warp per (direction, node).
// ---------------------------------------------------------------------------
__global__ __launch_bounds__(256) void gather_kernel(
    const float* __restrict__ bias_u, const float* __restrict__ bias_v,
    float* __restrict__ out) {
    const int dir = blockIdx.y;
    const int node = blockIdx.x * 8 + (threadIdx.x >> 5);
    if (node >= N_NODES) return;
    const int lane = threadIdx.x & 31;

    const int* offs = g_offs[dir];
    const int2* __restrict__ ent = dir ? g_ent_v : g_ent_u;
    const float* bias = dir ? bias_v : bias_u;

    const int beg = __ldg(offs + node);
    const int end = __ldg(offs + node + 1);

    float2 acc = make_float2(0.f, 0.f);
    int k = beg;
    for (; k + 3 < end; k += 4) {
        int2 e0 = __ldg(ent + k);
        int2 e1 = __ldg(ent + k + 1);
        int2 e2 = __ldg(ent + k + 2);
        int2 e3 = __ldg(ent + k + 3);
        __half2 r0 = *reinterpret_cast<const __half2*>(
            g_tmp + (size_t)e0.x * DIM + lane * 2);
        __half2 r1 = *reinterpret_cast<const __half2*>(
            g_tmp + (size_t)e1.x * DIM + lane * 2);
        __half2 r2 = *reinterpret_cast<const __half2*>(
            g_tmp + (size_t)e2.x * DIM + lane * 2);
        __half2 r3 = *reinterpret_cast<const __half2*>(
            g_tmp + (size_t)e3.x * DIM + lane * 2);
        float2 f0 = __half22float2(r0);
        float2 f1 = __half22float2(r1);
        float2 f2 = __half22float2(r2);
        float2 f3 = __half22float2(r3);
        float v0 = __int_as_float(e0.y);
        float v1 = __int_as_float(e1.y);
        float v2 = __int_as_float(e2.y);
        float v3 = __int_as_float(e3.y);
        acc.x = fmaf(v0, f0.x, acc.x);
        acc.y = fmaf(v0, f0.y, acc.y);
        acc.x = fmaf(v1, f1.x, acc.x);
        acc.y = fmaf(v1, f1.y, acc.y);
        acc.x = fmaf(v2, f2.x, acc.x);
        acc.y = fmaf(v2, f2.y, acc.y);
        acc.x = fmaf(v3, f3.x, acc.x);
        acc.y = fmaf(v3, f3.y, acc.y);
    }
    for (; k < end; k++) {
        int2 e0 = __ldg(ent + k);
        __half2 r0 = *reinterpret_cast<const __half2*>(
            g_tmp + (size_t)e0.x * DIM + lane * 2);
        float2 f0 = __half22float2(r0);
        float v0 = __int_as_float(e0.y);
        acc.x = fmaf(v0, f0.x, acc.x);
        acc.y = fmaf(v0, f0.y, acc.y);
    }

    float2 b = *reinterpret_cast<const float2*>(bias + lane * 2);
    acc.x += b.x;
    acc.y += b.y;
    acc.x = acc.x > 0.f ? acc.x : 0.f;
    acc.y = acc.y > 0.f ? acc.y : 0.f;
    *reinterpret_cast<float2*>(out + ((size_t)dir * N_NODES + node) * DIM +
                               lane * 2) = acc;
}

// ---------------------------------------------------------------------------
// Fork-join launch: GEMM branch (main) overlaps CSR branch (side).
// ---------------------------------------------------------------------------
extern "C" void kernel_launch(void* const* d_in, const int* in_sizes, int n_in,
                              void* d_out, int out_size) {
    const float* x_u = (const float*)d_in[0];
    const float* x_v = (const float*)d_in[1];
    const float* w_u = (const float*)d_in[2];
    const float* w_v = (const float*)d_in[3];
    const float* bias_u = (const float*)d_in[4];
    const float* bias_v = (const float*)d_in[5];
    const float* edge_val = (const float*)d_in[6];
    const int* edge_u = (const int*)d_in[7];
    const int* edge_v = (const int*)d_in[8];
    float* out = (float*)d_out;

    static cudaStream_t s_side = 0;
    static cudaEvent_t ev_fork = 0, ev_join = 0;
    if (!s_side) {
        cudaStreamCreateWithFlags(&s_side, cudaStreamNonBlocking);
        cudaEventCreateWithFlags(&ev_fork, cudaEventDisableTiming);
        cudaEventCreateWithFlags(&ev_join, cudaEventDisableTiming);
    }
    const int eblocks = (NEDGE + 255) / 256;  // 9766

    cudaEventRecord(ev_fork, 0);
    cudaStreamWaitEvent(s_side, ev_fork, 0);

    // Branch A (main): cumsum+transpose -> tensor-core GEMM.
    cumsum_kernel<<<16, 256>>>(w_u, w_v);
    dim3 ggrid((N_NODES + 127) / 128, 2);
    tmp_gemm_kernel<<<ggrid, 256>>>(x_u, x_v);

    // Branch B (side): CSR build, independent of GEMM.
    zero_deg_kernel<<<(N_NODES + 255) / 256, 256, 0, s_side>>>();
    hist_kernel<<<eblocks, 256, 0, s_side>>>(edge_u, edge_v);
    dim3 sgrid(SCAN_BLOCKS, 2);
    partial_kernel<<<sgrid, 256, 0, s_side>>>();
    scan_bsums_kernel<<<1, 2 * SCAN_BLOCKS, 0, s_side>>>();
    offsets_kernel<<<sgrid, 256, 0, s_side>>>();
    fill_kernel<<<eblocks, 256, 0, s_side>>>(edge_val, edge_u, edge_v);

    cudaEventRecord(ev_join, s_side);
    cudaStreamWaitEvent(0, ev_join, 0);

    dim3 agrid((N_NODES + 7) / 8, 2);
    gather_kernel<<<agrid, 256>>>(bias_u, bias_v, out);
}

// round 16
// speedup vs baseline: 1.0079x; 1.0079x over previous
#include <cuda_runtime.h>
#include <cuda_fp16.h>

#define N_NODES 100000
#define DIM 64
#define R 5
#define E 500000
#define NEDGE (R * E)  // 2.5M per direction
#define SCAN_BLOCKS 128
#define SCAN_CH ((N_NODES + SCAN_BLOCKS - 1) / SCAN_BLOCKS)  // 782
#define SCAN_SUB ((SCAN_CH + 255) / 256)                     // 4
#define XPITCH 72  // halves; pitch-72 makes all fragment LDS conflict-free

// Per-relation, per-direction transformed features in fp16: 128 MB.
// Slice index = r*2+dir, so each gather direction touches a disjoint 64 MB.
__device__ __align__(16) __half g_tmp[(size_t)R * 2 * N_NODES * DIM];
// Cumulative weights, fp16, TRANSPOSED [r][o][d] (o-major) per direction.
__device__ __align__(16) __half g_WcT_u[R * DIM * DIM];
__device__ __align__(16) __half g_WcT_v[R * DIM * DIM];

// CSR structures (destination-sorted edge lists), per direction.
__device__ int g_deg[2][N_NODES];
__device__ int g_offs[2][N_NODES + 1];
__device__ int g_cur[2][N_NODES];
__device__ int g_bsum[2 * SCAN_BLOCKS];
__device__ int g_bbase[2 * SCAN_BLOCKS];
__device__ __align__(16) int2 g_ent_u[NEDGE];  // {tmp_row_idx, bits(val)}
__device__ __align__(16) int2 g_ent_v[NEDGE];

// ---------------------------------------------------------------------------
// Cumsum of weights + fp16 transpose: g_WcT[r][o*64+d] = fp16(cumsum W[.][d][o]).
// ---------------------------------------------------------------------------
__global__ void cumsum_kernel(const float* __restrict__ wu,
                              const float* __restrict__ wv) {
    int t = blockIdx.x * blockDim.x + threadIdx.x;
    if (t >= DIM * DIM) return;
    int d = t >> 6, o = t & 63;
    float a = 0.f, b = 0.f;
#pragma unroll
    for (int r = 0; r < R; r++) {
        a += wu[r * DIM * DIM + t];
        b += wv[r * DIM * DIM + t];
        g_WcT_u[r * DIM * DIM + o * DIM + d] = __float2half_rn(a);
        g_WcT_v[r * DIM * DIM + o * DIM + d] = __float2half_rn(b);
    }
}

// ---------------------------------------------------------------------------
__global__ void zero_deg_kernel() {
    int i = blockIdx.x * blockDim.x + threadIdx.x;
    if (i < N_NODES) {
        g_deg[0][i] = 0;
        g_deg[1][i] = 0;
    }
}

// ---------------------------------------------------------------------------
// Degree histogram: fire-and-forget atomics (REDG), result unused. (R14 form —
// capturing the return value regressed hist 29->47 us in R15.)
// ---------------------------------------------------------------------------
__global__ __launch_bounds__(256) void hist_kernel(
    const int* __restrict__ edge_u, const int* __restrict__ edge_v) {
    long i = (long)blockIdx.x * blockDim.x + threadIdx.x;
    if (i >= NEDGE) return;
    atomicAdd(&g_deg[0][__ldg(edge_u + i)], 1);
    atomicAdd(&g_deg[1][__ldg(edge_v + i)], 1);
}

// ---------------------------------------------------------------------------
__global__ __launch_bounds__(256) void partial_kernel() {
    __shared__ int s[256];
    const int dir = blockIdx.y;
    const int base = blockIdx.x * SCAN_CH;
    const int t = threadIdx.x;
    int sum = 0;
    for (int i = t; i < SCAN_CH; i += 256) {
        int n = base + i;
        if (n < N_NODES) sum += g_deg[dir][n];
    }
    s[t] = sum;
    __syncthreads();
    for (int off = 128; off > 0; off >>= 1) {
        if (t < off) s[t] += s[t + off];
        __syncthreads();
    }
    if (t == 0) g_bsum[dir * SCAN_BLOCKS + blockIdx.x] = s[0];
}

// ---------------------------------------------------------------------------
__global__ __launch_bounds__(2 * SCAN_BLOCKS) void scan_bsums_kernel() {
    __shared__ int s[2 * SCAN_BLOCKS];
    const int t = threadIdx.x;
    const int idx = t & (SCAN_BLOCKS - 1);
    int my = g_bsum[t];
    s[t] = my;
    __syncthreads();
    for (int off = 1; off < SCAN_BLOCKS; off <<= 1) {
        int v = (idx >= off) ? s[t - off] : 0;
        __syncthreads();
        s[t] += v;
        __syncthreads();
    }
    g_bbase[t] = s[t] - my;  // exclusive
    if (idx == SCAN_BLOCKS - 1) g_offs[t >> 7][N_NODES] = s[t];
}

// ---------------------------------------------------------------------------
__global__ __launch_bounds__(256) void offsets_kernel() {
    __shared__ int s[256];
    const int dir = blockIdx.y;
    const int cbase = blockIdx.x * SCAN_CH;
    const int t = threadIdx.x;
    const int beg = cbase + t * SCAN_SUB;
    const int end = min(beg + SCAN_SUB, min(cbase + SCAN_CH, N_NODES));

    int d[SCAN_SUB];
    int sum = 0;
#pragma unroll
    for (int j = 0; j < SCAN_SUB; j++) {
        int n = beg + j;
        d[j] = (n < end) ? g_deg[dir][n] : 0;
        sum += d[j];
    }
    s[t] = sum;
    __syncthreads();
    for (int off = 1; off < 256; off <<= 1) {
        int v = (t >= off) ? s[t - off] : 0;
        __syncthreads();
        s[t] += v;
        __syncthreads();
    }
    int run = g_bbase[dir * SCAN_BLOCKS + blockIdx.x] + s[t] - sum;
#pragma unroll
    for (int j = 0; j < SCAN_SUB; j++) {
        int n = beg + j;
        if (n < end) {
            g_offs[dir][n] = run;
            g_cur[dir][n] = run;
            run += d[j];
        }
    }
}

// ---------------------------------------------------------------------------
// Fill CSR entries (R14 form: one returning atomic per edge per direction).
// ---------------------------------------------------------------------------
__global__ __launch_bounds__(256) void fill_kernel(
    const float* __restrict__ edge_val, const int* __restrict__ edge_u,
    const int* __restrict__ edge_v) {
    long i = (long)blockIdx.x * blockDim.x + threadIdx.x;
    if (i >= NEDGE) return;
    const int r = (int)(i / E);
    const int u = __ldg(edge_u + i);
    const int v = __ldg(edge_v + i);
    const int vb = __float_as_int(__ldg(edge_val + i));

    int pu = atomicAdd(&g_cur[0][u], 1);
    g_ent_u[pu] = make_int2((r * 2 + 1) * N_NODES + v, vb);
    int pv = atomicAdd(&g_cur[1][v], 1);
    g_ent_v[pv] = make_int2((r * 2 + 0) * N_NODES + u, vb);
}

// ---------------------------------------------------------------------------
// Tensor-core tmp GEMM (unchanged from R14 — validated).
// ---------------------------------------------------------------------------
__device__ __forceinline__ void mma16816(float c[4], const unsigned a[4],
                                         const unsigned b[2]) {
    asm volatile(
        "mma.sync.aligned.m16n8k16.row.col.f32.f16.f16.f32 "
        "{%0,%1,%2,%3}, {%4,%5,%6,%7}, {%8,%9}, {%0,%1,%2,%3};"
        : "+f"(c[0]), "+f"(c[1]), "+f"(c[2]), "+f"(c[3])
        : "r"(a[0]), "r"(a[1]), "r"(a[2]), "r"(a[3]), "r"(b[0]), "r"(b[1]));
}

__global__ __launch_bounds__(256) void tmp_gemm_kernel(
    const float* __restrict__ x_u, const float* __restrict__ x_v) {
    __shared__ __half x_sh[128 * XPITCH];  // 18 KB
    __shared__ __half w_shT[64 * XPITCH];  // 9 KB, [o][d]

    const int dir = blockIdx.y;
    const float* __restrict__ X = dir ? x_v : x_u;
    const __half* __restrict__ WTbase = dir ? g_WcT_v : g_WcT_u;

    const int nbase = blockIdx.x * 128;
    const int tid = threadIdx.x;
    const int lane = tid & 31;
    const int wid = tid >> 5;
    const int m_base = (wid >> 1) * 32;  // warp M origin
    const int n0w = (wid & 1) * 32;      // warp N origin

    for (int i = tid; i < 128 * 16; i += 256) {
        int row = i >> 4, c4 = i & 15;
        int gn = nbase + row;
        float4 v = make_float4(0.f, 0.f, 0.f, 0.f);
        if (gn < N_NODES)
            v = reinterpret_cast<const float4*>(X + (size_t)gn * DIM)[c4];
        __half2* p = reinterpret_cast<__half2*>(x_sh + row * XPITCH + c4 * 4);
        p[0] = __floats2half2_rn(v.x, v.y);
        p[1] = __floats2half2_rn(v.z, v.w);
    }

    const int frow = lane >> 2;     // fragment row (m or n) index
    const int fk = (lane & 3) * 2;  // fragment k pair base

    for (int r = 0; r < R; r++) {
        __syncthreads();
        const uint4* WT =
            reinterpret_cast<const uint4*>(WTbase + r * DIM * DIM);
#pragma unroll
        for (int it = 0; it < 2; it++) {
            int i = tid + it * 256;
            int row = i >> 3, d8 = i & 7;
            *reinterpret_cast<uint4*>(w_shT + row * XPITCH + d8 * 8) = WT[i];
        }
        __syncthreads();

        float c[2][4][4];
#pragma unroll
        for (int mt = 0; mt < 2; mt++)
#pragma unroll
            for (int nt = 0; nt < 4; nt++)
#pragma unroll
                for (int j = 0; j < 4; j++) c[mt][nt][j] = 0.f;

#pragma unroll
        for (int k0 = 0; k0 < 64; k0 += 16) {
            unsigned a[2][4];
#pragma unroll
            for (int mt = 0; mt < 2; mt++) {
                const __half* base =
                    x_sh + (m_base + mt * 16 + frow) * XPITCH + k0 + fk;
                a[mt][0] = *reinterpret_cast<const unsigned*>(base);
                a[mt][1] = *reinterpret_cast<const unsigned*>(base + 8 * XPITCH);
                a[mt][2] = *reinterpret_cast<const unsigned*>(base + 8);
                a[mt][3] =
                    *reinterpret_cast<const unsigned*>(base + 8 * XPITCH + 8);
            }
            unsigned b[4][2];
#pragma unroll
            for (int nt = 0; nt < 4; nt++) {
                const __half* wb =
                    w_shT + (n0w + nt * 8 + frow) * XPITCH + k0 + fk;
                b[nt][0] = *reinterpret_cast<const unsigned*>(wb);
                b[nt][1] = *reinterpret_cast<const unsigned*>(wb + 8);
            }
#pragma unroll
            for (int mt = 0; mt < 2; mt++)
#pragma unroll
                for (int nt = 0; nt < 4; nt++) mma16816(c[mt][nt], a[mt], b[nt]);
        }

        __half* T = g_tmp + (size_t)(r * 2 + dir) * N_NODES * DIM;
        const int ccol = (lane & 3) * 2;
#pragma unroll
        for (int mt = 0; mt < 2; mt++) {
            int gn0 = nbase + m_base + mt * 16 + frow;
            int gn1 = gn0 + 8;
#pragma unroll
            for (int nt = 0; nt < 4; nt++) {
                int o = n0w + nt * 8 + ccol;
                if (gn0 < N_NODES)
                    *reinterpret_cast<__half2*>(T + (size_t)gn0 * DIM + o) =
                        __floats2half2_rn(c[mt][nt][0], c[mt][nt][1]);
                if (gn1 < N_NODES)
                    *reinterpret_cast<__half2*>(T + (size_t)gn1 * DIM + o) =
                        __floats2half2_rn(c[mt][nt][2], c[mt][nt][3]);
            }
        }
    }
}

// ---------------------------------------------------------------------------
// Gather for ONE direction (dir as kernel arg; launched sequentially so each
// phase's random-read working set (~64 MB tmp slice half + 20 MB entries)
// fits in L2 — the concurrent-dir version thrashed (~170 MB > 126 MB L2).
// ---------------------------------------------------------------------------
__global__ __launch_bounds__(256) void gather_kernel(
    const float* __restrict__ bias_u, const float* __restrict__ bias_v,
    float* __restrict__ out, int dir) {
    const int node = blockIdx.x * 8 + (threadIdx.x >> 5);
    if (node >= N_NODES) return;
    const int lane = threadIdx.x & 31;

    const int* offs = g_offs[dir];
    const int2* __restrict__ ent = dir ? g_ent_v : g_ent_u;
    const float* bias = dir ? bias_v : bias_u;

    const int beg = __ldg(offs + node);
    const int end = __ldg(offs + node + 1);

    float2 acc = make_float2(0.f, 0.f);
    int k = beg;
    for (; k + 3 < end; k += 4) {
        int2 e0 = __ldg(ent + k);
        int2 e1 = __ldg(ent + k + 1);
        int2 e2 = __ldg(ent + k + 2);
        int2 e3 = __ldg(ent + k + 3);
        __half2 r0 = *reinterpret_cast<const __half2*>(
            g_tmp + (size_t)e0.x * DIM + lane * 2);
        __half2 r1 = *reinterpret_cast<const __half2*>(
            g_tmp + (size_t)e1.x * DIM + lane * 2);
        __half2 r2 = *reinterpret_cast<const __half2*>(
            g_tmp + (size_t)e2.x * DIM + lane * 2);
        __half2 r3 = *reinterpret_cast<const __half2*>(
            g_tmp + (size_t)e3.x * DIM + lane * 2);
        float2 f0 = __half22float2(r0);
        float2 f1 = __half22float2(r1);
        float2 f2 = __half22float2(r2);
        float2 f3 = __half22float2(r3);
        float v0 = __int_as_float(e0.y);
        float v1 = __int_as_float(e1.y);
        float v2 = __int_as_float(e2.y);
        float v3 = __int_as_float(e3.y);
        acc.x = fmaf(v0, f0.x, acc.x);
        acc.y = fmaf(v0, f0.y, acc.y);
        acc.x = fmaf(v1, f1.x, acc.x);
        acc.y = fmaf(v1, f1.y, acc.y);
        acc.x = fmaf(v2, f2.x, acc.x);
        acc.y = fmaf(v2, f2.y, acc.y);
        acc.x = fmaf(v3, f3.x, acc.x);
        acc.y = fmaf(v3, f3.y, acc.y);
    }
    for (; k < end; k++) {
        int2 e0 = __ldg(ent + k);
        __half2 r0 = *reinterpret_cast<const __half2*>(
            g_tmp + (size_t)e0.x * DIM + lane * 2);
        float2 f0 = __half22float2(r0);
        float v0 = __int_as_float(e0.y);
        acc.x = fmaf(v0, f0.x, acc.x);
        acc.y = fmaf(v0, f0.y, acc.y);
    }

    float2 b = *reinterpret_cast<const float2*>(bias + lane * 2);
    acc.x += b.x;
    acc.y += b.y;
    acc.x = acc.x > 0.f ? acc.x : 0.f;
    acc.y = acc.y > 0.f ? acc.y : 0.f;
    *reinterpret_cast<float2*>(out + ((size_t)dir * N_NODES + node) * DIM +
                               lane * 2) = acc;
}

// ---------------------------------------------------------------------------
// Fork-join launch; gather split into two sequential direction phases.
// ---------------------------------------------------------------------------
extern "C" void kernel_launch(void* const* d_in, const int* in_sizes, int n_in,
                              void* d_out, int out_size) {
    const float* x_u = (const float*)d_in[0];
    const float* x_v = (const float*)d_in[1];
    const float* w_u = (const float*)d_in[2];
    const float* w_v = (const float*)d_in[3];
    const float* bias_u = (const float*)d_in[4];
    const float* bias_v = (const float*)d_in[5];
    const float* edge_val = (const float*)d_in[6];
    const int* edge_u = (const int*)d_in[7];
    const int* edge_v = (const int*)d_in[8];
    float* out = (float*)d_out;

    static cudaStream_t s_side = 0;
    static cudaEvent_t ev_fork = 0, ev_join = 0;
    if (!s_side) {
        cudaStreamCreateWithFlags(&s_side, cudaStreamNonBlocking);
        cudaEventCreateWithFlags(&ev_fork, cudaEventDisableTiming);
        cudaEventCreateWithFlags(&ev_join, cudaEventDisableTiming);
    }
    const int eblocks = (NEDGE + 255) / 256;  // 9766

    cudaEventRecord(ev_fork, 0);
    cudaStreamWaitEvent(s_side, ev_fork, 0);

    // Branch A (main): cumsum+transpose -> tensor-core GEMM.
    cumsum_kernel<<<16, 256>>>(w_u, w_v);
    dim3 ggrid((N_NODES + 127) / 128, 2);
    tmp_gemm_kernel<<<ggrid, 256>>>(x_u, x_v);

    // Branch B (side): CSR build, independent of GEMM.
    zero_deg_kernel<<<(N_NODES + 255) / 256, 256, 0, s_side>>>();
    hist_kernel<<<eblocks, 256, 0, s_side>>>(edge_u, edge_v);
    dim3 sgrid(SCAN_BLOCKS, 2);
    partial_kernel<<<sgrid, 256, 0, s_side>>>();
    scan_bsums_kernel<<<1, 2 * SCAN_BLOCKS, 0, s_side>>>();
    offsets_kernel<<<sgrid, 256, 0, s_side>>>();
    fill_kernel<<<eblocks, 256, 0, s_side>>>(edge_val, edge_u, edge_v);

    cudaEventRecord(ev_join, s_side);
    cudaStreamWaitEvent(0, ev_join, 0);

    // Sequential per-direction gather: each phase is L2-resident.
    const int agrid = (N_NODES + 7) / 8;
    gather_kernel<<<agrid, 256>>>(bias_u, bias_v, out, 0);
    gather_kernel<<<agrid, 256>>>(bias_u, bias_v, out, 1);
}

// round 17
// speedup vs baseline: 1.0447x; 1.0365x over previous
#include <cuda_runtime.h>
#include <cuda_fp16.h>

#define N_NODES 100000
#define DIM 64
#define R 5
#define E 500000
#define NEDGE (R * E)  // 2.5M per direction
#define SCAN_BLOCKS 128
#define SCAN_CH ((N_NODES + SCAN_BLOCKS - 1) / SCAN_BLOCKS)  // 782
#define SCAN_SUB ((SCAN_CH + 255) / 256)                     // 4
#define XPITCH 72  // halves; pitch-72 makes all fragment LDS conflict-free

// Per-relation, per-direction transformed features in fp16: 128 MB.
__device__ __align__(16) __half g_tmp[(size_t)R * 2 * N_NODES * DIM];
// Cumulative weights, fp16, TRANSPOSED [r][o][d] (o-major) per direction.
__device__ __align__(16) __half g_WcT_u[R * DIM * DIM];
__device__ __align__(16) __half g_WcT_v[R * DIM * DIM];

// CSR structures (destination-sorted edge lists), per direction.
__device__ int g_deg[2][N_NODES];
__device__ int g_offs[2][N_NODES + 1];
__device__ int g_cur[2][N_NODES];
__device__ int g_bsum[2 * SCAN_BLOCKS];
__device__ int g_bbase[2 * SCAN_BLOCKS];
__device__ __align__(16) int2 g_ent_u[NEDGE];  // {tmp_row_idx, bits(val)}
__device__ __align__(16) int2 g_ent_v[NEDGE];

// ---------------------------------------------------------------------------
// Cumsum of weights + fp16 transpose: g_WcT[r][o*64+d] = fp16(cumsum W[.][d][o]).
// ---------------------------------------------------------------------------
__global__ void cumsum_kernel(const float* __restrict__ wu,
                              const float* __restrict__ wv) {
    int t = blockIdx.x * blockDim.x + threadIdx.x;
    if (t >= DIM * DIM) return;
    int d = t >> 6, o = t & 63;
    float a = 0.f, b = 0.f;
#pragma unroll
    for (int r = 0; r < R; r++) {
        a += wu[r * DIM * DIM + t];
        b += wv[r * DIM * DIM + t];
        g_WcT_u[r * DIM * DIM + o * DIM + d] = __float2half_rn(a);
        g_WcT_v[r * DIM * DIM + o * DIM + d] = __float2half_rn(b);
    }
}

// ---------------------------------------------------------------------------
__global__ void zero_deg_kernel() {
    int i = blockIdx.x * blockDim.x + threadIdx.x;
    if (i < N_NODES) {
        g_deg[0][i] = 0;
        g_deg[1][i] = 0;
    }
}

// ---------------------------------------------------------------------------
// Degree histogram: fire-and-forget atomics (REDG), result unused.
// ---------------------------------------------------------------------------
__global__ __launch_bounds__(256) void hist_kernel(
    const int* __restrict__ edge_u, const int* __restrict__ edge_v) {
    long i = (long)blockIdx.x * blockDim.x + threadIdx.x;
    if (i >= NEDGE) return;
    atomicAdd(&g_deg[0][__ldg(edge_u + i)], 1);
    atomicAdd(&g_deg[1][__ldg(edge_v + i)], 1);
}

// ---------------------------------------------------------------------------
__global__ __launch_bounds__(256) void partial_kernel() {
    __shared__ int s[256];
    const int dir = blockIdx.y;
    const int base = blockIdx.x * SCAN_CH;
    const int t = threadIdx.x;
    int sum = 0;
    for (int i = t; i < SCAN_CH; i += 256) {
        int n = base + i;
        if (n < N_NODES) sum += g_deg[dir][n];
    }
    s[t] = sum;
    __syncthreads();
    for (int off = 128; off > 0; off >>= 1) {
        if (t < off) s[t] += s[t + off];
        __syncthreads();
    }
    if (t == 0) g_bsum[dir * SCAN_BLOCKS + blockIdx.x] = s[0];
}

// ---------------------------------------------------------------------------
__global__ __launch_bounds__(2 * SCAN_BLOCKS) void scan_bsums_kernel() {
    __shared__ int s[2 * SCAN_BLOCKS];
    const int t = threadIdx.x;
    const int idx = t & (SCAN_BLOCKS - 1);
    int my = g_bsum[t];
    s[t] = my;
    __syncthreads();
    for (int off = 1; off < SCAN_BLOCKS; off <<= 1) {
        int v = (idx >= off) ? s[t - off] : 0;
        __syncthreads();
        s[t] += v;
        __syncthreads();
    }
    g_bbase[t] = s[t] - my;  // exclusive
    if (idx == SCAN_BLOCKS - 1) g_offs[t >> 7][N_NODES] = s[t];
}

// ---------------------------------------------------------------------------
__global__ __launch_bounds__(256) void offsets_kernel() {
    __shared__ int s[256];
    const int dir = blockIdx.y;
    const int cbase = blockIdx.x * SCAN_CH;
    const int t = threadIdx.x;
    const int beg = cbase + t * SCAN_SUB;
    const int end = min(beg + SCAN_SUB, min(cbase + SCAN_CH, N_NODES));

    int d[SCAN_SUB];
    int sum = 0;
#pragma unroll
    for (int j = 0; j < SCAN_SUB; j++) {
        int n = beg + j;
        d[j] = (n < end) ? g_deg[dir][n] : 0;
        sum += d[j];
    }
    s[t] = sum;
    __syncthreads();
    for (int off = 1; off < 256; off <<= 1) {
        int v = (t >= off) ? s[t - off] : 0;
        __syncthreads();
        s[t] += v;
        __syncthreads();
    }
    int run = g_bbase[dir * SCAN_BLOCKS + blockIdx.x] + s[t] - sum;
#pragma unroll
    for (int j = 0; j < SCAN_SUB; j++) {
        int n = beg + j;
        if (n < end) {
            g_offs[dir][n] = run;
            g_cur[dir][n] = run;
            run += d[j];
        }
    }
}

// ---------------------------------------------------------------------------
// Fill CSR entries for the U direction only (dst = edge_u).
// ---------------------------------------------------------------------------
__global__ __launch_bounds__(256) void fill_u_kernel(
    const float* __restrict__ edge_val, const int* __restrict__ edge_u,
    const int* __restrict__ edge_v) {
    long i = (long)blockIdx.x * blockDim.x + threadIdx.x;
    if (i >= NEDGE) return;
    const int r = (int)(i / E);
    const int u = __ldg(edge_u + i);
    const int v = __ldg(edge_v + i);
    const int vb = __float_as_int(__ldg(edge_val + i));
    int pu = atomicAdd(&g_cur[0][u], 1);
    g_ent_u[pu] = make_int2((r * 2 + 1) * N_NODES + v, vb);
}

// ---------------------------------------------------------------------------
// Fill CSR entries for the V direction only (dst = edge_v).
// ---------------------------------------------------------------------------
__global__ __launch_bounds__(256) void fill_v_kernel(
    const float* __restrict__ edge_val, const int* __restrict__ edge_u,
    const int* __restrict__ edge_v) {
    long i = (long)blockIdx.x * blockDim.x + threadIdx.x;
    if (i >= NEDGE) return;
    const int r = (int)(i / E);
    const int u = __ldg(edge_u + i);
    const int v = __ldg(edge_v + i);
    const int vb = __float_as_int(__ldg(edge_val + i));
    int pv = atomicAdd(&g_cur[1][v], 1);
    g_ent_v[pv] = make_int2((r * 2 + 0) * N_NODES + u, vb);
}

// ---------------------------------------------------------------------------
// Tensor-core tmp GEMM (unchanged — validated).
// ---------------------------------------------------------------------------
__device__ __forceinline__ void mma16816(float c[4], const unsigned a[4],
                                         const unsigned b[2]) {
    asm volatile(
        "mma.sync.aligned.m16n8k16.row.col.f32.f16.f16.f32 "
        "{%0,%1,%2,%3}, {%4,%5,%6,%7}, {%8,%9}, {%0,%1,%2,%3};"
        : "+f"(c[0]), "+f"(c[1]), "+f"(c[2]), "+f"(c[3])
        : "r"(a[0]), "r"(a[1]), "r"(a[2]), "r"(a[3]), "r"(b[0]), "r"(b[1]));
}

__global__ __launch_bounds__(256) void tmp_gemm_kernel(
    const float* __restrict__ x_u, const float* __restrict__ x_v) {
    __shared__ __half x_sh[128 * XPITCH];  // 18 KB
    __shared__ __half w_shT[64 * XPITCH];  // 9 KB, [o][d]

    const int dir = blockIdx.y;
    const float* __restrict__ X = dir ? x_v : x_u;
    const __half* __restrict__ WTbase = dir ? g_WcT_v : g_WcT_u;

    const int nbase = blockIdx.x * 128;
    const int tid = threadIdx.x;
    const int lane = tid & 31;
    const int wid = tid >> 5;
    const int m_base = (wid >> 1) * 32;  // warp M origin
    const int n0w = (wid & 1) * 32;      // warp N origin

    for (int i = tid; i < 128 * 16; i += 256) {
        int row = i >> 4, c4 = i & 15;
        int gn = nbase + row;
        float4 v = make_float4(0.f, 0.f, 0.f, 0.f);
        if (gn < N_NODES)
            v = reinterpret_cast<const float4*>(X + (size_t)gn * DIM)[c4];
        __half2* p = reinterpret_cast<__half2*>(x_sh + row * XPITCH + c4 * 4);
        p[0] = __floats2half2_rn(v.x, v.y);
        p[1] = __floats2half2_rn(v.z, v.w);
    }

    const int frow = lane >> 2;     // fragment row (m or n) index
    const int fk = (lane & 3) * 2;  // fragment k pair base

    for (int r = 0; r < R; r++) {
        __syncthreads();
        const uint4* WT =
            reinterpret_cast<const uint4*>(WTbase + r * DIM * DIM);
#pragma unroll
        for (int it = 0; it < 2; it++) {
            int i = tid + it * 256;
            int row = i >> 3, d8 = i & 7;
            *reinterpret_cast<uint4*>(w_shT + row * XPITCH + d8 * 8) = WT[i];
        }
        __syncthreads();

        float c[2][4][4];
#pragma unroll
        for (int mt = 0; mt < 2; mt++)
#pragma unroll
            for (int nt = 0; nt < 4; nt++)
#pragma unroll
                for (int j = 0; j < 4; j++) c[mt][nt][j] = 0.f;

#pragma unroll
        for (int k0 = 0; k0 < 64; k0 += 16) {
            unsigned a[2][4];
#pragma unroll
            for (int mt = 0; mt < 2; mt++) {
                const __half* base =
                    x_sh + (m_base + mt * 16 + frow) * XPITCH + k0 + fk;
                a[mt][0] = *reinterpret_cast<const unsigned*>(base);
                a[mt][1] = *reinterpret_cast<const unsigned*>(base + 8 * XPITCH);
                a[mt][2] = *reinterpret_cast<const unsigned*>(base + 8);
                a[mt][3] =
                    *reinterpret_cast<const unsigned*>(base + 8 * XPITCH + 8);
            }
            unsigned b[4][2];
#pragma unroll
            for (int nt = 0; nt < 4; nt++) {
                const __half* wb =
                    w_shT + (n0w + nt * 8 + frow) * XPITCH + k0 + fk;
                b[nt][0] = *reinterpret_cast<const unsigned*>(wb);
                b[nt][1] = *reinterpret_cast<const unsigned*>(wb + 8);
            }
#pragma unroll
            for (int mt = 0; mt < 2; mt++)
#pragma unroll
                for (int nt = 0; nt < 4; nt++) mma16816(c[mt][nt], a[mt], b[nt]);
        }

        __half* T = g_tmp + (size_t)(r * 2 + dir) * N_NODES * DIM;
        const int ccol = (lane & 3) * 2;
#pragma unroll
        for (int mt = 0; mt < 2; mt++) {
            int gn0 = nbase + m_base + mt * 16 + frow;
            int gn1 = gn0 + 8;
#pragma unroll
            for (int nt = 0; nt < 4; nt++) {
                int o = n0w + nt * 8 + ccol;
                if (gn0 < N_NODES)
                    *reinterpret_cast<__half2*>(T + (size_t)gn0 * DIM + o) =
                        __floats2half2_rn(c[mt][nt][0], c[mt][nt][1]);
                if (gn1 < N_NODES)
                    *reinterpret_cast<__half2*>(T + (size_t)gn1 * DIM + o) =
                        __floats2half2_rn(c[mt][nt][2], c[mt][nt][3]);
            }
        }
    }
}

// ---------------------------------------------------------------------------
// Gather for one direction (validated form).
// ---------------------------------------------------------------------------
__global__ __launch_bounds__(256) void gather_kernel(
    const float* __restrict__ bias_u, const float* __restrict__ bias_v,
    float* __restrict__ out, int dir) {
    const int node = blockIdx.x * 8 + (threadIdx.x >> 5);
    if (node >= N_NODES) return;
    const int lane = threadIdx.x & 31;

    const int* offs = g_offs[dir];
    const int2* __restrict__ ent = dir ? g_ent_v : g_ent_u;
    const float* bias = dir ? bias_v : bias_u;

    const int beg = __ldg(offs + node);
    const int end = __ldg(offs + node + 1);

    float2 acc = make_float2(0.f, 0.f);
    int k = beg;
    for (; k + 3 < end; k += 4) {
        int2 e0 = __ldg(ent + k);
        int2 e1 = __ldg(ent + k + 1);
        int2 e2 = __ldg(ent + k + 2);
        int2 e3 = __ldg(ent + k + 3);
        __half2 r0 = *reinterpret_cast<const __half2*>(
            g_tmp + (size_t)e0.x * DIM + lane * 2);
        __half2 r1 = *reinterpret_cast<const __half2*>(
            g_tmp + (size_t)e1.x * DIM + lane * 2);
        __half2 r2 = *reinterpret_cast<const __half2*>(
            g_tmp + (size_t)e2.x * DIM + lane * 2);
        __half2 r3 = *reinterpret_cast<const __half2*>(
            g_tmp + (size_t)e3.x * DIM + lane * 2);
        float2 f0 = __half22float2(r0);
        float2 f1 = __half22float2(r1);
        float2 f2 = __half22float2(r2);
        float2 f3 = __half22float2(r3);
        float v0 = __int_as_float(e0.y);
        float v1 = __int_as_float(e1.y);
        float v2 = __int_as_float(e2.y);
        float v3 = __int_as_float(e3.y);
        acc.x = fmaf(v0, f0.x, acc.x);
        acc.y = fmaf(v0, f0.y, acc.y);
        acc.x = fmaf(v1, f1.x, acc.x);
        acc.y = fmaf(v1, f1.y, acc.y);
        acc.x = fmaf(v2, f2.x, acc.x);
        acc.y = fmaf(v2, f2.y, acc.y);
        acc.x = fmaf(v3, f3.x, acc.x);
        acc.y = fmaf(v3, f3.y, acc.y);
    }
    for (; k < end; k++) {
        int2 e0 = __ldg(ent + k);
        __half2 r0 = *reinterpret_cast<const __half2*>(
            g_tmp + (size_t)e0.x * DIM + lane * 2);
        float2 f0 = __half22float2(r0);
        float v0 = __int_as_float(e0.y);
        acc.x = fmaf(v0, f0.x, acc.x);
        acc.y = fmaf(v0, f0.y, acc.y);
    }

    float2 b = *reinterpret_cast<const float2*>(bias + lane * 2);
    acc.x += b.x;
    acc.y += b.y;
    acc.x = acc.x > 0.f ? acc.x : 0.f;
    acc.y = acc.y > 0.f ? acc.y : 0.f;
    *reinterpret_cast<float2*>(out + ((size_t)dir * N_NODES + node) * DIM +
                               lane * 2) = acc;
}

// ---------------------------------------------------------------------------
// Pipelined launch:
//   side: zero → hist → scans → fill_u —ev_fu→ fill_v —ev_fv→
//   main: cumsum → gemm → (wait ev_fu) gather0 → (wait ev_fv) gather1
// gather0 overlaps fill_v (complementary: L2-reads vs atomics/stores).
// ---------------------------------------------------------------------------
extern "C" void kernel_launch(void* const* d_in, const int* in_sizes, int n_in,
                              void* d_out, int out_size) {
    const float* x_u = (const float*)d_in[0];
    const float* x_v = (const float*)d_in[1];
    const float* w_u = (const float*)d_in[2];
    const float* w_v = (const float*)d_in[3];
    const float* bias_u = (const float*)d_in[4];
    const float* bias_v = (const float*)d_in[5];
    const float* edge_val = (const float*)d_in[6];
    const int* edge_u = (const int*)d_in[7];
    const int* edge_v = (const int*)d_in[8];
    float* out = (float*)d_out;

    static cudaStream_t s_side = 0;
    static cudaEvent_t ev_fork = 0, ev_fu = 0, ev_fv = 0;
    if (!s_side) {
        cudaStreamCreateWithFlags(&s_side, cudaStreamNonBlocking);
        cudaEventCreateWithFlags(&ev_fork, cudaEventDisableTiming);
        cudaEventCreateWithFlags(&ev_fu, cudaEventDisableTiming);
        cudaEventCreateWithFlags(&ev_fv, cudaEventDisableTiming);
    }
    const int eblocks = (NEDGE + 255) / 256;  // 9766

    cudaEventRecord(ev_fork, 0);
    cudaStreamWaitEvent(s_side, ev_fork, 0);

    // Branch A (main): cumsum+transpose -> tensor-core GEMM.
    cumsum_kernel<<<16, 256>>>(w_u, w_v);
    dim3 ggrid((N_NODES + 127) / 128, 2);
    tmp_gemm_kernel<<<ggrid, 256>>>(x_u, x_v);

    // Branch B (side): CSR build, then per-direction fills.
    zero_deg_kernel<<<(N_NODES + 255) / 256, 256, 0, s_side>>>();
    hist_kernel<<<eblocks, 256, 0, s_side>>>(edge_u, edge_v);
    dim3 sgrid(SCAN_BLOCKS, 2);
    partial_kernel<<<sgrid, 256, 0, s_side>>>();
    scan_bsums_kernel<<<1, 2 * SCAN_BLOCKS, 0, s_side>>>();
    offsets_kernel<<<sgrid, 256, 0, s_side>>>();
    fill_u_kernel<<<eblocks, 256, 0, s_side>>>(edge_val, edge_u, edge_v);
    cudaEventRecord(ev_fu, s_side);
    fill_v_kernel<<<eblocks, 256, 0, s_side>>>(edge_val, edge_u, edge_v);
    cudaEventRecord(ev_fv, s_side);

    // Main: gather0 after gemm (program order) + fill_u; overlaps fill_v.
    const int agrid = (N_NODES + 7) / 8;
    cudaStreamWaitEvent(0, ev_fu, 0);
    gather_kernel<<<agrid, 256>>>(bias_u, bias_v, out, 0);
    cudaStreamWaitEvent(0, ev_fv, 0);
    gather_kernel<<<agrid, 256>>>(bias_u, bias_v, out, 1);
}